// round 1
// baseline (speedup 1.0000x reference)
#include <cuda_runtime.h>
#include <math.h>

#define N_ATOMS 100000
#define N_MOLS  5000
#define IN_F    1008
#define H1      256
#define H2      192
#define H3      160
#define CALPHA  0.1f
#define TILE    24
#define TPB     256
#define KC      144        // 1008 = 7 * 144
#define NCHUNK  7
#define NTILES  ((N_ATOMS + TILE - 1) / TILE)   // 4167

// ---------------- device scratch (no allocations allowed) ----------------
__device__ int g_type[N_ATOMS];
__device__ int g_sorted[N_ATOMS];
__device__ int g_counts[5];
__device__ int g_offsets[5];
__device__ int g_cursor[5];
__device__ int g_is64;

// ---------------- small plumbing kernels ----------------
__global__ void k_init(const int* __restrict__ z32) {
    if (threadIdx.x == 0 && blockIdx.x == 0) {
        // int64 detection: valid z values are in {1,6,7,8,9} (never 0).
        // If serialized as int64 (LE), the odd 32-bit words are all-zero high words.
        int is64 = (z32[1] == 0 && z32[3] == 0 && z32[5] == 0 && z32[7] == 0) ? 1 : 0;
        g_is64 = is64;
        for (int t = 0; t < 5; t++) { g_counts[t] = 0; g_cursor[t] = 0; }
    }
}

__global__ void k_zero_out(float* out, int n) {
    int i = blockIdx.x * blockDim.x + threadIdx.x;
    if (i < n) out[i] = 0.0f;
}

__device__ __forceinline__ int z_to_type(int zv) {
    return (zv == 1) ? 0 : (zv == 6) ? 1 : (zv == 7) ? 2 : (zv == 8) ? 3 : 4;
}

__global__ void k_count(const int* __restrict__ z32) {
    int i = blockIdx.x * blockDim.x + threadIdx.x;
    if (i >= N_ATOMS) return;
    int zv = g_is64 ? z32[2 * i] : z32[i];
    int t = z_to_type(zv);
    g_type[i] = t;
    atomicAdd(&g_counts[t], 1);
}

__global__ void k_scan() {
    if (threadIdx.x == 0 && blockIdx.x == 0) {
        int acc = 0;
        for (int t = 0; t < 5; t++) { g_offsets[t] = acc; acc += g_counts[t]; }
    }
}

__global__ void k_scatter() {
    int i = blockIdx.x * blockDim.x + threadIdx.x;
    if (i >= N_ATOMS) return;
    int t = g_type[i];
    int pos = g_offsets[t] + atomicAdd(&g_cursor[t], 1);
    g_sorted[pos] = i;
}

// ---------------- fused per-type 4-layer MLP + segment sum ----------------
// Grid: (NTILES, 5). Block: 256 threads. Each block processes TILE=24 atoms
// of one element type. Thread tid owns output column tid of each layer.
__device__ __forceinline__ float celu_f(float x) {
    return x > 0.0f ? x : CALPHA * expm1f(x * (1.0f / CALPHA));
}

__global__ void __launch_bounds__(TPB, 4)
k_mlp(const float* __restrict__ feat,
      const int*   __restrict__ batch32,
      const float* __restrict__ W1, const float* __restrict__ b1,
      const float* __restrict__ W2, const float* __restrict__ b2,
      const float* __restrict__ W3, const float* __restrict__ b3,
      const float* __restrict__ W4, const float* __restrict__ b4,
      float* __restrict__ out)
{
    const int t = blockIdx.y;
    const int cnt = g_counts[t];
    const int start = blockIdx.x * TILE;
    if (start >= cnt) return;
    const int nact = min(TILE, cnt - start);

    // Static shared buffers (43 KB total):
    //   sA: feat chunk [TILE][KC] during layer1, then h2 [TILE][H2]
    //   sB: h1 [TILE][H1] during layer2, then h3 [TILE][H3]
    __shared__ __align__(16) float sA[TILE * H2];   // 4608 floats (>= TILE*KC=3456)
    __shared__ __align__(16) float sB[TILE * H1];   // 6144 floats
    __shared__ int s_ids[TILE];

    const int tid = threadIdx.x;
    if (tid < TILE) {
        s_ids[tid] = (tid < nact) ? g_sorted[g_offsets[t] + start + tid] : -1;
    }

    const int h = tid;  // column index, 0..255

    // ---------------- Layer 1: [TILE x 1008] @ [1008 x 256] ----------------
    float acc[TILE];
#pragma unroll
    for (int a = 0; a < TILE; a++) acc[a] = 0.0f;

    const float* W1t = W1 + t * (IN_F * H1);

    for (int c = 0; c < NCHUNK; c++) {
        const int f0 = c * KC;
        __syncthreads();
        // cooperative load of feature chunk: TILE*KC/4 = 864 float4
        for (int idx4 = tid; idx4 < TILE * (KC / 4); idx4 += TPB) {
            const int a  = idx4 / (KC / 4);
            const int fq = idx4 % (KC / 4);
            float4 v = make_float4(0.f, 0.f, 0.f, 0.f);
            if (a < nact) {
                const int id = s_ids[a];
                v = *reinterpret_cast<const float4*>(&feat[(size_t)id * IN_F + f0 + 4 * fq]);
            }
            reinterpret_cast<float4*>(sA)[idx4] = v;
        }
        __syncthreads();

        const float* p = W1t + f0 * H1 + h;
#pragma unroll 2
        for (int f = 0; f < KC; f += 4) {
            const float w0 = __ldg(p);
            const float w1 = __ldg(p + H1);
            const float w2 = __ldg(p + 2 * H1);
            const float w3 = __ldg(p + 3 * H1);
            p += 4 * H1;
            const int fq = f >> 2;
#pragma unroll
            for (int a = 0; a < TILE; a++) {
                float4 x = reinterpret_cast<const float4*>(sA)[a * (KC / 4) + fq];
                acc[a] = fmaf(w0, x.x, fmaf(w1, x.y, fmaf(w2, x.z, fmaf(w3, x.w, acc[a]))));
            }
        }
    }
    __syncthreads();
    {
        const float bb = b1[t * H1 + h];
#pragma unroll
        for (int a = 0; a < TILE; a++) {
            sB[a * H1 + h] = celu_f(acc[a] + bb);
        }
    }
    __syncthreads();

    // ---------------- Layer 2: [TILE x 256] @ [256 x 192] ----------------
    float acc2[TILE];
#pragma unroll
    for (int a = 0; a < TILE; a++) acc2[a] = 0.0f;

    if (h < H2) {
        const float* p = W2 + t * (H1 * H2) + h;
#pragma unroll 2
        for (int k = 0; k < H1; k += 4) {
            const float w0 = __ldg(p);
            const float w1 = __ldg(p + H2);
            const float w2 = __ldg(p + 2 * H2);
            const float w3 = __ldg(p + 3 * H2);
            p += 4 * H2;
            const int kq = k >> 2;
#pragma unroll
            for (int a = 0; a < TILE; a++) {
                float4 x = reinterpret_cast<const float4*>(sB)[a * (H1 / 4) + kq];
                acc2[a] = fmaf(w0, x.x, fmaf(w1, x.y, fmaf(w2, x.z, fmaf(w3, x.w, acc2[a]))));
            }
        }
    }
    __syncthreads();   // done reading sA's previous contents (none) & layer-1 acc phase
    if (h < H2) {
        const float bb = b2[t * H2 + h];
#pragma unroll
        for (int a = 0; a < TILE; a++) {
            sA[a * H2 + h] = celu_f(acc2[a] + bb);
        }
    }
    __syncthreads();

    // ---------------- Layer 3: [TILE x 192] @ [192 x 160] ----------------
    float acc3[TILE];
#pragma unroll
    for (int a = 0; a < TILE; a++) acc3[a] = 0.0f;

    if (h < H3) {
        const float* p = W3 + t * (H2 * H3) + h;
#pragma unroll 2
        for (int k = 0; k < H2; k += 4) {
            const float w0 = __ldg(p);
            const float w1 = __ldg(p + H3);
            const float w2 = __ldg(p + 2 * H3);
            const float w3 = __ldg(p + 3 * H3);
            p += 4 * H3;
            const int kq = k >> 2;
#pragma unroll
            for (int a = 0; a < TILE; a++) {
                float4 x = reinterpret_cast<const float4*>(sA)[a * (H2 / 4) + kq];
                acc3[a] = fmaf(w0, x.x, fmaf(w1, x.y, fmaf(w2, x.z, fmaf(w3, x.w, acc3[a]))));
            }
        }
    }
    __syncthreads();   // sB (h1) no longer needed
    if (h < H3) {
        const float bb = b3[t * H3 + h];
#pragma unroll
        for (int a = 0; a < TILE; a++) {
            sB[a * H3 + h] = celu_f(acc3[a] + bb);
        }
    }
    __syncthreads();

    // ---------------- Layer 4 + segment sum ----------------
    // 8 warps; warp w reduces atoms w*3 .. w*3+2 over H3=160 with lane-parallel dot.
    const int wid  = tid >> 5;
    const int lane = tid & 31;
    const float* W4t = W4 + t * H3;
    const float b4t = b4[t];

    for (int a = wid * 3; a < wid * 3 + 3; a++) {
        if (a >= nact) break;
        float p = 0.0f;
#pragma unroll
        for (int k = lane; k < H3; k += 32) {
            p = fmaf(sB[a * H3 + k], __ldg(&W4t[k]), p);
        }
#pragma unroll
        for (int off = 16; off; off >>= 1) p += __shfl_down_sync(0xffffffffu, p, off);
        if (lane == 0) {
            const int id  = s_ids[a];
            const int mol = g_is64 ? batch32[2 * id] : batch32[id];
            atomicAdd(&out[mol], p + b4t);
        }
    }
}

// ---------------- launch ----------------
extern "C" void kernel_launch(void* const* d_in, const int* in_sizes, int n_in,
                              void* d_out, int out_size) {
    const int*   z     = (const int*)  d_in[0];
    const float* feat  = (const float*)d_in[1];
    const int*   batch = (const int*)  d_in[2];
    // d_in[3] = n_mols (unused; compile-time constant)
    const float* W1 = (const float*)d_in[4];
    const float* b1 = (const float*)d_in[5];
    const float* W2 = (const float*)d_in[6];
    const float* b2 = (const float*)d_in[7];
    const float* W3 = (const float*)d_in[8];
    const float* b3 = (const float*)d_in[9];
    const float* W4 = (const float*)d_in[10];
    const float* b4 = (const float*)d_in[11];
    float* out = (float*)d_out;

    k_zero_out<<<(out_size + 255) / 256, 256>>>(out, out_size);
    k_init<<<1, 32>>>(z);
    k_count<<<(N_ATOMS + 255) / 256, 256>>>(z);
    k_scan<<<1, 1>>>();
    k_scatter<<<(N_ATOMS + 255) / 256, 256>>>();

    dim3 grid(NTILES, 5);
    k_mlp<<<grid, TPB>>>(feat, batch, W1, b1, W2, b2, W3, b3, W4, b4, out);
}

// round 3
// speedup vs baseline: 3.1919x; 3.1919x over previous
#include <cuda_runtime.h>
#include <math.h>
#include <stdint.h>

#define N_ATOMS 100000
#define IN_F    1008
#define KPAD    1024
#define H1      256
#define H2      192
#define H3      160
#define CALPHA  0.1f
#define MT      128
#define TPB     512
#define NT_MAX  ((N_ATOMS + MT - 1) / MT)   // 782

// ---------------- device scratch (static, no allocations) ----------------
__device__ int g_type[N_ATOMS];
__device__ int g_sorted[N_ATOMS];
__device__ int g_counts[5], g_offsets[5], g_cursor[5], g_is64;
__device__ float g_W1T[5 * H1 * KPAD];          // [t][n][kpad] tf32, zero-padded
__device__ float g_W2T[5 * H2 * H1];            // [t][n][k]    tf32
__device__ float g_W3T[5 * H3 * H2];            // [t][n][k]    tf32
__device__ float g_H1[(size_t)N_ATOMS * H1];    // tf32-rounded activations
__device__ float g_H2[(size_t)N_ATOMS * H2];

// ---------------- helpers ----------------
__device__ __forceinline__ uint32_t tf32r(float x) {
    uint32_t u; asm("cvt.rna.tf32.f32 %0, %1;" : "=r"(u) : "f"(x)); return u;
}
__device__ __forceinline__ float celu_f(float x) {
    return x > 0.0f ? x : CALPHA * expm1f(x * (1.0f / CALPHA));
}
__device__ __forceinline__ void cp16(uint32_t dst, const void* src, int valid) {
    asm volatile("cp.async.cg.shared.global [%0], [%1], 16, %2;"
                 :: "r"(dst), "l"(src), "r"(valid ? 16 : 0) : "memory");
}
#define CP_COMMIT() asm volatile("cp.async.commit_group;" ::: "memory")
#define CP_WAIT1()  asm volatile("cp.async.wait_group 1;" ::: "memory")
#define CP_WAIT0()  asm volatile("cp.async.wait_group 0;" ::: "memory")

#define MMA8(d, a, b0, b1) \
    asm volatile("mma.sync.aligned.m16n8k8.row.col.f32.tf32.tf32.f32 " \
                 "{%0,%1,%2,%3},{%4,%5,%6,%7},{%8,%9},{%0,%1,%2,%3};" \
                 : "+f"((d)[0]), "+f"((d)[1]), "+f"((d)[2]), "+f"((d)[3]) \
                 : "r"((a)[0]), "r"((a)[1]), "r"((a)[2]), "r"((a)[3]), \
                   "r"(b0), "r"(b1))

// ---------------- plumbing kernels ----------------
__global__ void k_init(const int* __restrict__ z32) {
    if (threadIdx.x == 0 && blockIdx.x == 0) {
        g_is64 = (z32[1] == 0 && z32[3] == 0 && z32[5] == 0 && z32[7] == 0) ? 1 : 0;
        for (int t = 0; t < 5; t++) { g_counts[t] = 0; g_cursor[t] = 0; }
    }
}
__global__ void k_zero_out(float* out, int n) {
    int i = blockIdx.x * blockDim.x + threadIdx.x;
    if (i < n) out[i] = 0.0f;
}
__device__ __forceinline__ int z_to_type(int zv) {
    return (zv == 1) ? 0 : (zv == 6) ? 1 : (zv == 7) ? 2 : (zv == 8) ? 3 : 4;
}
__global__ void k_count(const int* __restrict__ z32) {
    int i = blockIdx.x * blockDim.x + threadIdx.x;
    if (i >= N_ATOMS) return;
    int zv = g_is64 ? z32[2 * i] : z32[i];
    int t = z_to_type(zv);
    g_type[i] = t;
    atomicAdd(&g_counts[t], 1);
}
__global__ void k_scan() {
    if (threadIdx.x == 0 && blockIdx.x == 0) {
        int acc = 0;
        for (int t = 0; t < 5; t++) { g_offsets[t] = acc; acc += g_counts[t]; }
    }
}
__global__ void k_scatter() {
    int i = blockIdx.x * blockDim.x + threadIdx.x;
    if (i >= N_ATOMS) return;
    int t = g_type[i];
    int pos = g_offsets[t] + atomicAdd(&g_cursor[t], 1);
    g_sorted[pos] = i;
}

// weight transpose + tf32 round (+ K-pad for W1)
__global__ void k_prep_w1(const float* __restrict__ W1) {
    int i = blockIdx.x * blockDim.x + threadIdx.x;
    if (i >= 5 * H1 * KPAD) return;
    int kp = i & (KPAD - 1);
    int r = i >> 10;
    int n = r & (H1 - 1);
    int t = r >> 8;
    float v = (kp < IN_F) ? W1[((size_t)t * IN_F + kp) * H1 + n] : 0.0f;
    g_W1T[i] = __uint_as_float(tf32r(v));
}
__global__ void k_prep_w2(const float* __restrict__ W2) {
    int i = blockIdx.x * blockDim.x + threadIdx.x;
    if (i >= 5 * H2 * H1) return;
    int h = i & (H1 - 1);
    int r = i >> 8;
    int g = r % H2;
    int t = r / H2;
    g_W2T[i] = __uint_as_float(tf32r(W2[((size_t)t * H1 + h) * H2 + g]));
}
__global__ void k_prep_w3(const float* __restrict__ W3) {
    int i = blockIdx.x * blockDim.x + threadIdx.x;
    if (i >= 5 * H3 * H2) return;
    int g = i % H2;
    int r = i / H2;
    int k3 = r % H3;
    int t = r / H3;
    g_W3T[i] = __uint_as_float(tf32r(W3[((size_t)t * H2 + g) * H3 + k3]));
}

// ---------------- fused GEMM kernel (3 modes) ----------------
// MODE 1: A = features (gather via sorted ids, tf32 in fragment path), N=256, K=1024(pad)
//         epilogue: celu -> tf32 -> g_H1
// MODE 2: A = g_H1, N=192, K=256; epilogue: celu -> tf32 -> g_H2
// MODE 3: A = g_H2, N=160, K=192; epilogue: celu * W4 row-reduce -> atomicAdd out[mol]
template<int MODE>
__global__ void __launch_bounds__(TPB, 1)
k_gemm(const float* __restrict__ feat,
       const int*   __restrict__ batch32,
       const float* __restrict__ bias,     // 5*NN
       const float* __restrict__ W4,       // 5*H3 (MODE 3)
       const float* __restrict__ b4,       // 5    (MODE 3)
       float* __restrict__ out)            // MODE 3
{
    constexpr int NN   = (MODE == 1) ? H1 : (MODE == 2) ? H2 : H3;
    constexpr int KTOT = (MODE == 1) ? KPAD : (MODE == 2) ? H1 : H2;
    constexpr int KROW = KTOT;            // B row stride
    constexpr int NC   = KTOT / 32;
    constexpr int WNW  = NN / 4;          // cols per warp-column
    constexpr int NT8  = NN / 32;         // n8 tiles per warp

    const int t = blockIdx.y;
    const int cnt = g_counts[t];
    const int start = blockIdx.x * MT;
    if (start >= cnt) return;
    const int nact = min(MT, cnt - start);
    const int goff = g_offsets[t];

    extern __shared__ __align__(16) float smem[];
    float* sA = smem;                      // [2][MT][36]
    float* sB = smem + 2 * MT * 36;        // [2][NN][36]
    __shared__ int sids[MT];

    const int tid = threadIdx.x;
    const int wid = tid >> 5, lane = tid & 31;
    const int wm = wid & 3, wn = wid >> 2;
    const int g = lane >> 2, tig = lane & 3;

    if (tid < MT) sids[tid] = (tid < nact) ? g_sorted[goff + start + tid] : -1;
    __syncthreads();

    const uint32_t sA_u = (uint32_t)__cvta_generic_to_shared(sA);
    const uint32_t sB_u = (uint32_t)__cvta_generic_to_shared(sB);
    const float* Bsrc = ((MODE == 1) ? g_W1T : (MODE == 2) ? g_W2T : g_W3T)
                        + (size_t)t * NN * KROW;

    float acc[2][NT8][4];
#pragma unroll
    for (int i = 0; i < 2; i++)
#pragma unroll
        for (int j = 0; j < NT8; j++)
#pragma unroll
            for (int q = 0; q < 4; q++) acc[i][j][q] = 0.0f;

    auto issue = [&](int c) {
        const int s = c & 1;
        const int k0 = c * 32;
        // A tile: MT x 32 floats = 1024 float4
#pragma unroll
        for (int q = tid; q < MT * 8; q += TPB) {
            const int row = q >> 3, fq = q & 7;
            const uint32_t dst = sA_u + (((s * MT + row) * 36 + fq * 4) << 2);
            if (MODE == 1) {
                const int id = sids[row];
                const int k = k0 + fq * 4;
                const int v = (id >= 0) && (k < IN_F);
                const float* src = v ? feat + (size_t)id * IN_F + k : feat;
                cp16(dst, src, v);
            } else {
                const int p = goff + start + row;
                const int v = (p < N_ATOMS);
                const float* Asrc = (MODE == 2) ? g_H1 : g_H2;
                const float* src = v ? Asrc + (size_t)p * KTOT + k0 + fq * 4 : Asrc;
                cp16(dst, src, v);
            }
        }
        // B tile: NN x 32 floats
        for (int q = tid; q < NN * 8; q += TPB) {
            const int n = q >> 3, fq = q & 7;
            const uint32_t dst = sB_u + (((s * NN + n) * 36 + fq * 4) << 2);
            cp16(dst, Bsrc + (size_t)n * KROW + k0 + fq * 4, 1);
        }
        CP_COMMIT();
    };

    issue(0);
    for (int c = 0; c < NC; c++) {
        if (c + 1 < NC) { issue(c + 1); CP_WAIT1(); }
        else            { CP_WAIT0(); }
        __syncthreads();
        const float* A = sA + (c & 1) * MT * 36;
        const float* B = sB + (c & 1) * NN * 36;
#pragma unroll
        for (int kk = 0; kk < 4; kk++) {
            const int k = kk * 8;
            uint32_t af[2][4];
#pragma unroll
            for (int mt = 0; mt < 2; mt++) {
                const int r = wm * 32 + mt * 16 + g;
                if (MODE == 1) {
                    af[mt][0] = tf32r(A[r * 36 + k + tig]);
                    af[mt][1] = tf32r(A[(r + 8) * 36 + k + tig]);
                    af[mt][2] = tf32r(A[r * 36 + k + tig + 4]);
                    af[mt][3] = tf32r(A[(r + 8) * 36 + k + tig + 4]);
                } else {
                    af[mt][0] = __float_as_uint(A[r * 36 + k + tig]);
                    af[mt][1] = __float_as_uint(A[(r + 8) * 36 + k + tig]);
                    af[mt][2] = __float_as_uint(A[r * 36 + k + tig + 4]);
                    af[mt][3] = __float_as_uint(A[(r + 8) * 36 + k + tig + 4]);
                }
            }
#pragma unroll
            for (int nt = 0; nt < NT8; nt++) {
                const int n = wn * WNW + nt * 8 + g;
                const uint32_t b0 = __float_as_uint(B[n * 36 + k + tig]);
                const uint32_t b1 = __float_as_uint(B[n * 36 + k + tig + 4]);
                MMA8(acc[0][nt], af[0], b0, b1);
                MMA8(acc[1][nt], af[1], b0, b1);
            }
        }
        __syncthreads();
    }

    // ---------------- epilogue ----------------
    if (MODE == 3) {
        float part[2][2] = {{0.0f, 0.0f}, {0.0f, 0.0f}};
        const float* b3v = bias + t * H3;
        const float* w4v = W4 + t * H3;
#pragma unroll
        for (int nt = 0; nt < NT8; nt++) {
            const int c0 = wn * WNW + nt * 8 + 2 * tig;
            const float bb0 = __ldg(b3v + c0), bb1 = __ldg(b3v + c0 + 1);
            const float w0  = __ldg(w4v + c0), w1  = __ldg(w4v + c0 + 1);
#pragma unroll
            for (int mt = 0; mt < 2; mt++) {
                part[mt][0] += celu_f(acc[mt][nt][0] + bb0) * w0
                             + celu_f(acc[mt][nt][1] + bb1) * w1;
                part[mt][1] += celu_f(acc[mt][nt][2] + bb0) * w0
                             + celu_f(acc[mt][nt][3] + bb1) * w1;
            }
        }
#pragma unroll
        for (int mt = 0; mt < 2; mt++)
#pragma unroll
            for (int rh = 0; rh < 2; rh++) {
                part[mt][rh] += __shfl_xor_sync(0xffffffffu, part[mt][rh], 1);
                part[mt][rh] += __shfl_xor_sync(0xffffffffu, part[mt][rh], 2);
            }
        if (tig == 0) {
            const float b4v = __ldg(b4 + t);
#pragma unroll
            for (int mt = 0; mt < 2; mt++)
#pragma unroll
                for (int rh = 0; rh < 2; rh++) {
                    const int row = wm * 32 + mt * 16 + rh * 8 + g;
                    if (row < nact) {
                        const int id = sids[row];
                        const int mol = g_is64 ? batch32[2 * id] : batch32[id];
                        atomicAdd(&out[mol], part[mt][rh] + (wn == 0 ? b4v : 0.0f));
                    }
                }
        }
    } else {
        float* Hout = (MODE == 1) ? g_H1 : g_H2;
        const float* bv = bias + t * NN;
#pragma unroll
        for (int mt = 0; mt < 2; mt++) {
            const int r0 = wm * 32 + mt * 16 + g;
            const int r1 = r0 + 8;
#pragma unroll
            for (int nt = 0; nt < NT8; nt++) {
                const int c0 = wn * WNW + nt * 8 + 2 * tig;
                const float bb0 = __ldg(bv + c0), bb1 = __ldg(bv + c0 + 1);
                if (r0 < nact) {
                    float2 v;
                    v.x = __uint_as_float(tf32r(celu_f(acc[mt][nt][0] + bb0)));
                    v.y = __uint_as_float(tf32r(celu_f(acc[mt][nt][1] + bb1)));
                    *reinterpret_cast<float2*>(&Hout[(size_t)(goff + start + r0) * NN + c0]) = v;
                }
                if (r1 < nact) {
                    float2 v;
                    v.x = __uint_as_float(tf32r(celu_f(acc[mt][nt][2] + bb0)));
                    v.y = __uint_as_float(tf32r(celu_f(acc[mt][nt][3] + bb1)));
                    *reinterpret_cast<float2*>(&Hout[(size_t)(goff + start + r1) * NN + c0]) = v;
                }
            }
        }
    }
}

// ---------------- launch ----------------
#define SM1 ((2 * MT * 36 + 2 * H1 * 36) * 4)   // 110592
#define SM2 ((2 * MT * 36 + 2 * H2 * 36) * 4)   // 92160
#define SM3 ((2 * MT * 36 + 2 * H3 * 36) * 4)   // 82944

extern "C" void kernel_launch(void* const* d_in, const int* in_sizes, int n_in,
                              void* d_out, int out_size) {
    const int*   z     = (const int*)  d_in[0];
    const float* feat  = (const float*)d_in[1];
    const int*   batch = (const int*)  d_in[2];
    const float* W1 = (const float*)d_in[4];
    const float* b1 = (const float*)d_in[5];
    const float* W2 = (const float*)d_in[6];
    const float* b2 = (const float*)d_in[7];
    const float* W3 = (const float*)d_in[8];
    const float* b3 = (const float*)d_in[9];
    const float* W4 = (const float*)d_in[10];
    const float* b4 = (const float*)d_in[11];
    float* out = (float*)d_out;

    cudaFuncSetAttribute(k_gemm<1>, cudaFuncAttributeMaxDynamicSharedMemorySize, SM1);
    cudaFuncSetAttribute(k_gemm<2>, cudaFuncAttributeMaxDynamicSharedMemorySize, SM2);
    cudaFuncSetAttribute(k_gemm<3>, cudaFuncAttributeMaxDynamicSharedMemorySize, SM3);

    k_zero_out<<<(out_size + 255) / 256, 256>>>(out, out_size);
    k_init<<<1, 32>>>(z);
    k_count<<<(N_ATOMS + 255) / 256, 256>>>(z);
    k_scan<<<1, 1>>>();
    k_scatter<<<(N_ATOMS + 255) / 256, 256>>>();
    k_prep_w1<<<(5 * H1 * KPAD + 255) / 256, 256>>>(W1);
    k_prep_w2<<<(5 * H2 * H1 + 255) / 256, 256>>>(W2);
    k_prep_w3<<<(5 * H3 * H2 + 255) / 256, 256>>>(W3);

    dim3 grid(NT_MAX, 5);
    k_gemm<1><<<grid, TPB, SM1>>>(feat, batch, b1, W4, b4, out);
    k_gemm<2><<<grid, TPB, SM2>>>(feat, batch, b2, W4, b4, out);
    k_gemm<3><<<grid, TPB, SM3>>>(feat, batch, b3, W4, b4, out);
}

// round 4
// speedup vs baseline: 3.1984x; 1.0020x over previous
#include <cuda_runtime.h>
#include <math.h>
#include <stdint.h>

#define N_ATOMS 100000
#define IN_F    1008
#define KPAD    1024
#define H1      256
#define H2      192
#define H3      160
#define CALPHA  0.1f
#define MT      128
#define TPB     256
#define NT_MAX  ((N_ATOMS + MT - 1) / MT)   // 782

// ---------------- device scratch (static, no allocations) ----------------
__device__ int g_type[N_ATOMS];
__device__ int g_sorted[N_ATOMS];
__device__ int g_counts[5], g_offsets[5], g_cursor[5], g_is64;
// fragment-order permuted weights: [t][kc][n8][kk][lane][2]
__device__ float g_W1T[5 * H1 * KPAD];
__device__ float g_W2T[5 * H2 * H1];
__device__ float g_W3T[5 * H3 * H2];
__device__ float g_H1[(size_t)N_ATOMS * H1];    // tf32-rounded activations
__device__ float g_H2[(size_t)N_ATOMS * H2];

// ---------------- helpers ----------------
__device__ __forceinline__ uint32_t tf32r(float x) {
    uint32_t u; asm("cvt.rna.tf32.f32 %0, %1;" : "=r"(u) : "f"(x)); return u;
}
__device__ __forceinline__ float celu_f(float x) {
    return x > 0.0f ? x : CALPHA * expm1f(x * (1.0f / CALPHA));
}
__device__ __forceinline__ void cp16(uint32_t dst, const void* src, int valid) {
    asm volatile("cp.async.cg.shared.global [%0], [%1], 16, %2;"
                 :: "r"(dst), "l"(src), "r"(valid ? 16 : 0) : "memory");
}
#define CP_COMMIT() asm volatile("cp.async.commit_group;" ::: "memory")
#define CP_WAIT1()  asm volatile("cp.async.wait_group 1;" ::: "memory")
#define CP_WAIT0()  asm volatile("cp.async.wait_group 0;" ::: "memory")

#define MMA8(d, a, b0, b1) \
    asm volatile("mma.sync.aligned.m16n8k8.row.col.f32.tf32.tf32.f32 " \
                 "{%0,%1,%2,%3},{%4,%5,%6,%7},{%8,%9},{%0,%1,%2,%3};" \
                 : "+f"((d)[0]), "+f"((d)[1]), "+f"((d)[2]), "+f"((d)[3]) \
                 : "r"((a)[0]), "r"((a)[1]), "r"((a)[2]), "r"((a)[3]), \
                   "r"(b0), "r"(b1))

// ---------------- plumbing kernels ----------------
__global__ void k_init(const int* __restrict__ z32, float* out, int n_out) {
    int i = blockIdx.x * blockDim.x + threadIdx.x;
    if (i < n_out) out[i] = 0.0f;
    if (i == 0) {
        g_is64 = (z32[1] == 0 && z32[3] == 0 && z32[5] == 0 && z32[7] == 0) ? 1 : 0;
        for (int t = 0; t < 5; t++) { g_counts[t] = 0; g_cursor[t] = 0; }
    }
}
__device__ __forceinline__ int z_to_type(int zv) {
    return (zv == 1) ? 0 : (zv == 6) ? 1 : (zv == 7) ? 2 : (zv == 8) ? 3 : 4;
}
__global__ void k_count(const int* __restrict__ z32) {
    int i = blockIdx.x * blockDim.x + threadIdx.x;
    if (i >= N_ATOMS) return;
    int zv = g_is64 ? z32[2 * i] : z32[i];
    int t = z_to_type(zv);
    g_type[i] = t;
    atomicAdd(&g_counts[t], 1);
}
__global__ void k_scan() {
    if (threadIdx.x == 0 && blockIdx.x == 0) {
        int acc = 0;
        for (int t = 0; t < 5; t++) { g_offsets[t] = acc; acc += g_counts[t]; }
    }
}
__global__ void k_scatter() {
    int i = blockIdx.x * blockDim.x + threadIdx.x;
    if (i >= N_ATOMS) return;
    int t = g_type[i];
    int pos = g_offsets[t] + atomicAdd(&g_cursor[t], 1);
    g_sorted[pos] = i;
}

// one prep kernel: permute all 3 weight sets into fragment order + tf32 round.
// dst flat index i decodes as (t, kc, n8, kk, lane, j):
//   n = n8*8 + (lane>>2); k = kc*32 + kk*8 + (lane&3) + 4*j
__device__ __forceinline__ void prep_one(float* dst, const float* src,
                                         int NN, int KTOT, int KIN, int i) {
    const int j    = i & 1;
    const int lane = (i >> 1) & 31;
    const int kk   = (i >> 6) & 3;
    int rest = i >> 8;
    const int n8   = rest % (NN / 8);  rest /= (NN / 8);
    const int kc   = rest % (KTOT / 32);
    const int t    = rest / (KTOT / 32);
    const int n = n8 * 8 + (lane >> 2);
    const int k = kc * 32 + kk * 8 + (lane & 3) + 4 * j;
    float v = (k < KIN) ? src[((size_t)t * KIN + k) * NN + n] : 0.0f;
    dst[i] = __uint_as_float(tf32r(v));
}
__global__ void k_prep(const float* __restrict__ W1, const float* __restrict__ W2,
                       const float* __restrict__ W3) {
    int i = blockIdx.x * blockDim.x + threadIdx.x;
    if (blockIdx.y == 0) {
        if (i < 5 * H1 * KPAD) prep_one(g_W1T, W1, H1, KPAD, IN_F, i);
    } else if (blockIdx.y == 1) {
        if (i < 5 * H2 * H1) prep_one(g_W2T, W2, H2, H1, H1, i);
    } else {
        if (i < 5 * H3 * H2) prep_one(g_W3T, W3, H3, H2, H2, i);
    }
}

// ---------------- fused GEMM kernel (3 modes) ----------------
// 256 threads = 8 warps as 2(M) x 4(N); warp tile 64 x (NN/4); mt=4.
template<int MODE>
__global__ void __launch_bounds__(TPB, 1)
k_gemm(const float* __restrict__ feat,
       const int*   __restrict__ batch32,
       const float* __restrict__ bias,
       const float* __restrict__ W4,
       const float* __restrict__ b4,
       float* __restrict__ out)
{
    constexpr int NN   = (MODE == 1) ? H1 : (MODE == 2) ? H2 : H3;
    constexpr int KTOT = (MODE == 1) ? KPAD : (MODE == 2) ? H1 : H2;
    constexpr int NC   = KTOT / 32;
    constexpr int NT8  = NN / 32;         // n8-tiles per warp (8/6/5)

    const int t = blockIdx.y;
    const int cnt = g_counts[t];
    const int start = blockIdx.x * MT;
    if (start >= cnt) return;
    const int nact = min(MT, cnt - start);
    const int goff = g_offsets[t];

    extern __shared__ __align__(16) float smem[];
    float* sA = smem;                      // [2][MT][36]
    float* sB = smem + 2 * MT * 36;        // [2][NN*32] fragment order
    __shared__ int sids[MT];

    const int tid = threadIdx.x;
    const int wid = tid >> 5, lane = tid & 31;
    const int wm = wid & 1, wn = wid >> 1;
    const int g = lane >> 2, tig = lane & 3;

    if (tid < MT) sids[tid] = (tid < nact) ? g_sorted[goff + start + tid] : -1;
    __syncthreads();

    const uint32_t sA_u = (uint32_t)__cvta_generic_to_shared(sA);
    const uint32_t sB_u = (uint32_t)__cvta_generic_to_shared(sB);
    const float* Bbase = (MODE == 1) ? g_W1T : (MODE == 2) ? g_W2T : g_W3T;
    const float* Bt = Bbase + (size_t)t * NN * KTOT;   // chunk c at + c*NN*32

    float acc[4][NT8][4];
#pragma unroll
    for (int i = 0; i < 4; i++)
#pragma unroll
        for (int j = 0; j < NT8; j++)
#pragma unroll
            for (int q = 0; q < 4; q++) acc[i][j][q] = 0.0f;

    auto issue = [&](int c) {
        const int s = c & 1;
        const int k0 = c * 32;
        // A tile: MT x 32 floats = 1024 float4
#pragma unroll
        for (int q = tid; q < MT * 8; q += TPB) {
            const int row = q >> 3, fq = q & 7;
            const uint32_t dst = sA_u + (((s * MT + row) * 36 + fq * 4) << 2);
            if (MODE == 1) {
                const int id = sids[row];
                const int k = k0 + fq * 4;
                const int v = (id >= 0) && (k < IN_F);
                const float* src = v ? feat + (size_t)id * IN_F + k : feat;
                cp16(dst, src, v);
            } else {
                const int p = goff + start + row;
                const int v = (p < N_ATOMS);
                const float* Asrc = (MODE == 2) ? g_H1 : g_H2;
                const float* src = v ? Asrc + (size_t)p * KTOT + k0 + fq * 4 : Asrc;
                cp16(dst, src, v);
            }
        }
        // B tile: contiguous NN*32 floats (fragment order)
        const float* bsrc = Bt + (size_t)c * NN * 32;
#pragma unroll
        for (int q = tid; q < NN * 8; q += TPB) {
            cp16(sB_u + ((s * NN * 32 + q * 4) << 2), bsrc + q * 4, 1);
        }
        CP_COMMIT();
    };

    issue(0);
    for (int c = 0; c < NC; c++) {
        if (c + 1 < NC) { issue(c + 1); CP_WAIT1(); }
        else            { CP_WAIT0(); }
        __syncthreads();
        const float* A = sA + (c & 1) * MT * 36;
        const float* B = sB + (c & 1) * NN * 32;
#pragma unroll
        for (int kk = 0; kk < 4; kk++) {
            const int k = kk * 8;
            uint32_t af[4][4];
#pragma unroll
            for (int mt = 0; mt < 4; mt++) {
                const int r = wm * 64 + mt * 16 + g;
                if (MODE == 1) {
                    af[mt][0] = tf32r(A[r * 36 + k + tig]);
                    af[mt][1] = tf32r(A[(r + 8) * 36 + k + tig]);
                    af[mt][2] = tf32r(A[r * 36 + k + tig + 4]);
                    af[mt][3] = tf32r(A[(r + 8) * 36 + k + tig + 4]);
                } else {
                    af[mt][0] = __float_as_uint(A[r * 36 + k + tig]);
                    af[mt][1] = __float_as_uint(A[(r + 8) * 36 + k + tig]);
                    af[mt][2] = __float_as_uint(A[r * 36 + k + tig + 4]);
                    af[mt][3] = __float_as_uint(A[(r + 8) * 36 + k + tig + 4]);
                }
            }
#pragma unroll
            for (int nt = 0; nt < NT8; nt++) {
                const int n8 = wn * NT8 + nt;
                const float2 bb = *reinterpret_cast<const float2*>(
                    B + (n8 * 4 + kk) * 64 + lane * 2);
                const uint32_t b0 = __float_as_uint(bb.x);
                const uint32_t b1 = __float_as_uint(bb.y);
#pragma unroll
                for (int mt = 0; mt < 4; mt++) MMA8(acc[mt][nt], af[mt], b0, b1);
            }
        }
        __syncthreads();
    }

    // ---------------- epilogue ----------------
    if (MODE == 3) {
        float part[4][2];
#pragma unroll
        for (int mt = 0; mt < 4; mt++) { part[mt][0] = 0.0f; part[mt][1] = 0.0f; }
        const float* b3v = bias + t * H3;
        const float* w4v = W4 + t * H3;
#pragma unroll
        for (int nt = 0; nt < NT8; nt++) {
            const int c0 = wn * (NN / 4) + nt * 8 + 2 * tig;
            const float bb0 = __ldg(b3v + c0), bb1 = __ldg(b3v + c0 + 1);
            const float w0  = __ldg(w4v + c0), w1  = __ldg(w4v + c0 + 1);
#pragma unroll
            for (int mt = 0; mt < 4; mt++) {
                part[mt][0] += celu_f(acc[mt][nt][0] + bb0) * w0
                             + celu_f(acc[mt][nt][1] + bb1) * w1;
                part[mt][1] += celu_f(acc[mt][nt][2] + bb0) * w0
                             + celu_f(acc[mt][nt][3] + bb1) * w1;
            }
        }
#pragma unroll
        for (int mt = 0; mt < 4; mt++)
#pragma unroll
            for (int rh = 0; rh < 2; rh++) {
                part[mt][rh] += __shfl_xor_sync(0xffffffffu, part[mt][rh], 1);
                part[mt][rh] += __shfl_xor_sync(0xffffffffu, part[mt][rh], 2);
            }
        if (tig == 0) {
            const float b4v = __ldg(b4 + t);
#pragma unroll
            for (int mt = 0; mt < 4; mt++)
#pragma unroll
                for (int rh = 0; rh < 2; rh++) {
                    const int row = wm * 64 + mt * 16 + rh * 8 + g;
                    if (row < nact) {
                        const int id = sids[row];
                        const int mol = g_is64 ? batch32[2 * id] : batch32[id];
                        atomicAdd(&out[mol], part[mt][rh] + (wn == 0 ? b4v : 0.0f));
                    }
                }
        }
    } else {
        float* Hout = (MODE == 1) ? g_H1 : g_H2;
        const float* bv = bias + t * NN;
#pragma unroll
        for (int mt = 0; mt < 4; mt++) {
            const int r0 = wm * 64 + mt * 16 + g;
            const int r1 = r0 + 8;
#pragma unroll
            for (int nt = 0; nt < NT8; nt++) {
                const int c0 = wn * (NN / 4) + nt * 8 + 2 * tig;
                const float bb0 = __ldg(bv + c0), bb1 = __ldg(bv + c0 + 1);
                if (r0 < nact) {
                    float2 v;
                    v.x = __uint_as_float(tf32r(celu_f(acc[mt][nt][0] + bb0)));
                    v.y = __uint_as_float(tf32r(celu_f(acc[mt][nt][1] + bb1)));
                    *reinterpret_cast<float2*>(&Hout[(size_t)(goff + start + r0) * NN + c0]) = v;
                }
                if (r1 < nact) {
                    float2 v;
                    v.x = __uint_as_float(tf32r(celu_f(acc[mt][nt][2] + bb0)));
                    v.y = __uint_as_float(tf32r(celu_f(acc[mt][nt][3] + bb1)));
                    *reinterpret_cast<float2*>(&Hout[(size_t)(goff + start + r1) * NN + c0]) = v;
                }
            }
        }
    }
}

// ---------------- launch ----------------
#define SM1 ((2 * MT * 36 + 2 * H1 * 32) * 4)   // 102400
#define SM2 ((2 * MT * 36 + 2 * H2 * 32) * 4)   // 86016
#define SM3 ((2 * MT * 36 + 2 * H3 * 32) * 4)   // 77824

extern "C" void kernel_launch(void* const* d_in, const int* in_sizes, int n_in,
                              void* d_out, int out_size) {
    const int*   z     = (const int*)  d_in[0];
    const float* feat  = (const float*)d_in[1];
    const int*   batch = (const int*)  d_in[2];
    const float* W1 = (const float*)d_in[4];
    const float* b1 = (const float*)d_in[5];
    const float* W2 = (const float*)d_in[6];
    const float* b2 = (const float*)d_in[7];
    const float* W3 = (const float*)d_in[8];
    const float* b3 = (const float*)d_in[9];
    const float* W4 = (const float*)d_in[10];
    const float* b4 = (const float*)d_in[11];
    float* out = (float*)d_out;

    cudaFuncSetAttribute(k_gemm<1>, cudaFuncAttributeMaxDynamicSharedMemorySize, SM1);
    cudaFuncSetAttribute(k_gemm<2>, cudaFuncAttributeMaxDynamicSharedMemorySize, SM2);
    cudaFuncSetAttribute(k_gemm<3>, cudaFuncAttributeMaxDynamicSharedMemorySize, SM3);

    // launch order chosen so ncu (-s 5 -c 1) profiles k_gemm<1>
    k_init<<<(N_ATOMS + 255) / 256, 256>>>(z, out, out_size);          // 1
    k_count<<<(N_ATOMS + 255) / 256, 256>>>(z);                        // 2
    k_scan<<<1, 1>>>();                                                // 3
    k_scatter<<<(N_ATOMS + 255) / 256, 256>>>();                       // 4
    dim3 pg((5 * H1 * KPAD + 255) / 256, 3);
    k_prep<<<pg, 256>>>(W1, W2, W3);                                   // 5

    dim3 grid(NT_MAX, 5);
    k_gemm<1><<<grid, TPB, SM1>>>(feat, batch, b1, W4, b4, out);       // 6 <- profiled
    k_gemm<2><<<grid, TPB, SM2>>>(feat, batch, b2, W4, b4, out);
    k_gemm<3><<<grid, TPB, SM3>>>(feat, batch, b3, W4, b4, out);
}

// round 5
// speedup vs baseline: 4.1613x; 1.3011x over previous
#include <cuda_runtime.h>
#include <cuda_fp16.h>
#include <math.h>
#include <stdint.h>

#define N_ATOMS 100000
#define IN_F    1008
#define KPAD    1024
#define H1      256
#define H2      192
#define H3      160
#define CALPHA  0.1f
#define MT      128
#define TPB     256
#define NT_MAX  ((N_ATOMS + MT - 1) / MT)       // 782
#define NTILES_MAX (NT_MAX + 5)                 // 787 (per-type padding)
#define PAD_MAX (NTILES_MAX * MT)               // 100736

// ---------------- device scratch (static, no allocations) ----------------
__device__ int g_type[N_ATOMS];
__device__ int g_sorted[PAD_MAX];               // padded, -1 filled
__device__ int g_counts[5], g_poff[5], g_cursor[5], g_is64;
// fp16 fragment-order data
__device__ uint4 g_F16[(size_t)NTILES_MAX * 64 * 8 * 32];   // [tile][ks(64)][bm(8)][lane] ~206MB
__device__ uint4 g_H1f[(size_t)NTILES_MAX * 16 * 8 * 32];   // [tile][ks(16)][bm][lane]
__device__ uint4 g_H2f[(size_t)NTILES_MAX * 12 * 8 * 32];   // [tile][ks(12)][bm][lane]
__device__ uint2 g_W16_1[5 * H1 * KPAD / 4];    // [t][kc][n8][ks][lane]
__device__ uint2 g_W16_2[5 * H2 * H1 / 4];
__device__ uint2 g_W16_3[5 * H3 * H2 / 4];

// ---------------- helpers ----------------
__device__ __forceinline__ float celu_f(float x) {
    return x > 0.0f ? x : CALPHA * expm1f(x * (1.0f / CALPHA));
}
__device__ __forceinline__ uint32_t pack2(float a, float b) {
    __half2 h = __floats2half2_rn(a, b);
    return *reinterpret_cast<uint32_t*>(&h);
}
__device__ __forceinline__ void cp16(uint32_t dst, const void* src) {
    asm volatile("cp.async.cg.shared.global [%0], [%1], 16;"
                 :: "r"(dst), "l"(src) : "memory");
}
#define CP_COMMIT() asm volatile("cp.async.commit_group;" ::: "memory")
#define CP_WAIT1()  asm volatile("cp.async.wait_group 1;" ::: "memory")
#define CP_WAIT0()  asm volatile("cp.async.wait_group 0;" ::: "memory")

#define MMA16(d, a, b0, b1) \
    asm volatile("mma.sync.aligned.m16n8k16.row.col.f32.f16.f16.f32 " \
                 "{%0,%1,%2,%3},{%4,%5,%6,%7},{%8,%9},{%0,%1,%2,%3};" \
                 : "+f"((d)[0]), "+f"((d)[1]), "+f"((d)[2]), "+f"((d)[3]) \
                 : "r"((a).x), "r"((a).y), "r"((a).z), "r"((a).w), \
                   "r"(b0), "r"(b1))

// ---------------- plumbing kernels ----------------
__global__ void k_init(const int* __restrict__ z32, float* out, int n_out) {
    int i = blockIdx.x * blockDim.x + threadIdx.x;
    if (i < n_out) out[i] = 0.0f;
    if (i < PAD_MAX) g_sorted[i] = -1;
    if (i == 0) {
        g_is64 = (z32[1] == 0 && z32[3] == 0 && z32[5] == 0 && z32[7] == 0) ? 1 : 0;
        for (int t = 0; t < 5; t++) { g_counts[t] = 0; g_cursor[t] = 0; }
    }
}
__device__ __forceinline__ int z_to_type(int zv) {
    return (zv == 1) ? 0 : (zv == 6) ? 1 : (zv == 7) ? 2 : (zv == 8) ? 3 : 4;
}
__global__ void k_count(const int* __restrict__ z32) {
    int i = blockIdx.x * blockDim.x + threadIdx.x;
    if (i >= N_ATOMS) return;
    int zv = g_is64 ? z32[2 * i] : z32[i];
    int t = z_to_type(zv);
    g_type[i] = t;
    atomicAdd(&g_counts[t], 1);
}
__global__ void k_scan() {
    if (threadIdx.x == 0 && blockIdx.x == 0) {
        int acc = 0;
        for (int t = 0; t < 5; t++) {
            g_poff[t] = acc;
            acc += ((g_counts[t] + MT - 1) / MT) * MT;   // pad to tile multiple
        }
    }
}
__global__ void k_scatter() {
    int i = blockIdx.x * blockDim.x + threadIdx.x;
    if (i >= N_ATOMS) return;
    int t = g_type[i];
    int pos = g_poff[t] + atomicAdd(&g_cursor[t], 1);
    g_sorted[pos] = i;
}

// weight permute into fragment order, fp16
__device__ __forceinline__ void prep_w(uint2* dst, const float* src,
                                       int NN, int KTOT, int KIN, int i) {
    const int lane = i & 31;
    const int ks   = (i >> 5) & 3;
    int rest = i >> 7;
    const int n8 = rest % (NN / 8); rest /= (NN / 8);
    const int kc = rest % (KTOT / 64);
    const int t  = rest / (KTOT / 64);
    const int n = n8 * 8 + (lane >> 2);
    const int k0 = kc * 64 + ks * 16 + 2 * (lane & 3);
    const int k1 = k0 + 8;
    const float* W = src + (size_t)t * KIN * NN;
    float v00 = (k0 < KIN)     ? W[(size_t)k0 * NN + n]       : 0.0f;
    float v01 = (k0 + 1 < KIN) ? W[(size_t)(k0 + 1) * NN + n] : 0.0f;
    float v10 = (k1 < KIN)     ? W[(size_t)k1 * NN + n]       : 0.0f;
    float v11 = (k1 + 1 < KIN) ? W[(size_t)(k1 + 1) * NN + n] : 0.0f;
    dst[i] = make_uint2(pack2(v00, v01), pack2(v10, v11));
}

// combined prep: y=0 -> features (gather+sort+convert to fragment order), y=1 -> weights
__global__ void k_prep(const float* __restrict__ feat,
                       const float* __restrict__ W1, const float* __restrict__ W2,
                       const float* __restrict__ W3) {
    int i = blockIdx.x * blockDim.x + threadIdx.x;
    if (blockIdx.y == 1) {
        if (i < 5 * H1 * KPAD / 4) prep_w(g_W16_1, W1, H1, KPAD, IN_F, i);
        else if (i < 5 * H1 * KPAD / 4 + 5 * H2 * H1 / 4)
            prep_w(g_W16_2, W2, H2, H1, H1, i - 5 * H1 * KPAD / 4);
        else if (i < 5 * H1 * KPAD / 4 + 5 * H2 * H1 / 4 + 5 * H3 * H2 / 4)
            prep_w(g_W16_3, W3, H3, H2, H2, i - 5 * H1 * KPAD / 4 - 5 * H2 * H1 / 4);
        return;
    }
    // features: one uint4 (full A fragment) per thread
    // layout: [tile][ks(64)][bm(8)][lane(32)]
    if (i >= NTILES_MAX * 64 * 8 * 32) return;
    const int lane = i & 31;
    const int bm   = (i >> 5) & 7;
    const int ks   = (i >> 8) & 63;
    const int tile = i >> 14;
    const int g = lane >> 2, tig = lane & 3;
    const int row0 = tile * MT + bm * 16 + g;
    const int row1 = row0 + 8;
    const int id0 = g_sorted[row0];
    const int id1 = g_sorted[row1];
    const int k0 = ks * 16 + 2 * tig;
    const int k1 = k0 + 8;
    float2 f00 = make_float2(0.f, 0.f), f01 = make_float2(0.f, 0.f);
    float2 f10 = make_float2(0.f, 0.f), f11 = make_float2(0.f, 0.f);
    if (id0 >= 0) {
        if (k0 < IN_F) f00 = *reinterpret_cast<const float2*>(feat + (size_t)id0 * IN_F + k0);
        if (k1 < IN_F) f01 = *reinterpret_cast<const float2*>(feat + (size_t)id0 * IN_F + k1);
    }
    if (id1 >= 0) {
        if (k0 < IN_F) f10 = *reinterpret_cast<const float2*>(feat + (size_t)id1 * IN_F + k0);
        if (k1 < IN_F) f11 = *reinterpret_cast<const float2*>(feat + (size_t)id1 * IN_F + k1);
    }
    uint4 v;
    v.x = pack2(f00.x, f00.y);   // a0: row g,   k0..k0+1
    v.y = pack2(f10.x, f10.y);   // a1: row g+8, k0..k0+1
    v.z = pack2(f01.x, f01.y);   // a2: row g,   k1..k1+1
    v.w = pack2(f11.x, f11.y);   // a3: row g+8, k1..k1+1
    g_F16[i] = v;
}

// ---------------- fused fp16 GEMM kernel (3 modes) ----------------
// 256 threads = 8 warps as 2(M) x 4(N); warp tile 64 x (NN/4); K-chunks of 64.
template<int MODE>
__global__ void __launch_bounds__(TPB)
k_gemm(const int* __restrict__ batch32,
       const float* __restrict__ bias,
       const float* __restrict__ W4,
       const float* __restrict__ b4,
       float* __restrict__ out)
{
    constexpr int NN   = (MODE == 1) ? H1 : (MODE == 2) ? H2 : H3;
    constexpr int KTOT = (MODE == 1) ? KPAD : (MODE == 2) ? H1 : H2;
    constexpr int NCH  = KTOT / 64;           // 16 / 4 / 3
    constexpr int NT8  = NN / 32;             // 8 / 6 / 5
    constexpr int A_NKS = KTOT / 16;          // per-tile A k-steps
    constexpr int BCH  = NN * 8;              // B chunk size in uint4

    const int t = blockIdx.y;
    const int cnt = g_counts[t];
    const int start = blockIdx.x * MT;
    if (start >= cnt) return;
    const int nact = min(MT, cnt - start);
    const int tile = (g_poff[t] >> 7) + blockIdx.x;

    extern __shared__ __align__(16) uint4 smem[];
    uint4* sA = smem;                          // [2][1024]
    uint2* sB = reinterpret_cast<uint2*>(smem + 2048);   // [2][NN*16]
    __shared__ int sids[MT];

    const int tid = threadIdx.x;
    const int wid = tid >> 5, lane = tid & 31;
    const int wm = wid & 1, wn = wid >> 1;
    const int g = lane >> 2, tig = lane & 3;

    if (MODE == 3 && tid < MT) sids[tid] = g_sorted[tile * MT + tid];
    __syncthreads();

    const uint32_t sA_u = (uint32_t)__cvta_generic_to_shared(sA);
    const uint32_t sB_u = (uint32_t)__cvta_generic_to_shared(sB);
    const uint4* Asrc = ((MODE == 1) ? g_F16 : (MODE == 2) ? g_H1f : g_H2f)
                        + (size_t)tile * A_NKS * 256;
    const uint4* Bt = reinterpret_cast<const uint4*>(
                        (MODE == 1) ? g_W16_1 : (MODE == 2) ? g_W16_2 : g_W16_3)
                      + (size_t)t * NN * KTOT / 8;

    float acc[4][NT8][4];
#pragma unroll
    for (int i = 0; i < 4; i++)
#pragma unroll
        for (int j = 0; j < NT8; j++)
#pragma unroll
            for (int q = 0; q < 4; q++) acc[i][j][q] = 0.0f;

    auto issue = [&](int c) {
        const int s = c & 1;
        const uint4* a = Asrc + c * 1024;
#pragma unroll
        for (int q = tid; q < 1024; q += TPB)
            cp16(sA_u + ((s * 1024 + q) << 4), a + q);
        const uint4* b = Bt + (size_t)c * BCH;
#pragma unroll
        for (int q = tid; q < BCH; q += TPB)
            cp16(sB_u + ((s * BCH + q) << 4), b + q);
        CP_COMMIT();
    };

    issue(0);
    for (int c = 0; c < NCH; c++) {
        if (c + 1 < NCH) { issue(c + 1); CP_WAIT1(); }
        else             { CP_WAIT0(); }
        __syncthreads();
        const uint4* A = sA + (c & 1) * 1024;
        const uint2* B = sB + (c & 1) * NN * 16;
#pragma unroll
        for (int ksl = 0; ksl < 4; ksl++) {
            uint4 av[4];
#pragma unroll
            for (int mt = 0; mt < 4; mt++)
                av[mt] = A[(ksl * 8 + wm * 4 + mt) * 32 + lane];
#pragma unroll
            for (int nt = 0; nt < NT8; nt++) {
                const uint2 bv = B[((wn * NT8 + nt) * 4 + ksl) * 32 + lane];
#pragma unroll
                for (int mt = 0; mt < 4; mt++) MMA16(acc[mt][nt], av[mt], bv.x, bv.y);
            }
        }
        __syncthreads();
    }

    // ---------------- epilogue ----------------
    if (MODE == 3) {
        float part[4][2];
#pragma unroll
        for (int mt = 0; mt < 4; mt++) { part[mt][0] = 0.0f; part[mt][1] = 0.0f; }
        const float* b3v = bias + t * H3;
        const float* w4v = W4 + t * H3;
#pragma unroll
        for (int nt = 0; nt < NT8; nt++) {
            const int c0 = wn * (NN / 4) + nt * 8 + 2 * tig;
            const float bb0 = __ldg(b3v + c0), bb1 = __ldg(b3v + c0 + 1);
            const float w0  = __ldg(w4v + c0), w1  = __ldg(w4v + c0 + 1);
#pragma unroll
            for (int mt = 0; mt < 4; mt++) {
                part[mt][0] += celu_f(acc[mt][nt][0] + bb0) * w0
                             + celu_f(acc[mt][nt][1] + bb1) * w1;
                part[mt][1] += celu_f(acc[mt][nt][2] + bb0) * w0
                             + celu_f(acc[mt][nt][3] + bb1) * w1;
            }
        }
#pragma unroll
        for (int mt = 0; mt < 4; mt++)
#pragma unroll
            for (int rh = 0; rh < 2; rh++) {
                part[mt][rh] += __shfl_xor_sync(0xffffffffu, part[mt][rh], 1);
                part[mt][rh] += __shfl_xor_sync(0xffffffffu, part[mt][rh], 2);
            }
        if (tig == 0) {
            const float b4v = __ldg(b4 + t);
#pragma unroll
            for (int mt = 0; mt < 4; mt++)
#pragma unroll
                for (int rh = 0; rh < 2; rh++) {
                    const int row = wm * 64 + mt * 16 + rh * 8 + g;
                    if (row < nact) {
                        const int id = sids[row];
                        const int mol = g_is64 ? batch32[2 * id] : batch32[id];
                        atomicAdd(&out[mol], part[mt][rh] + (wn == 0 ? b4v : 0.0f));
                    }
                }
        }
    } else {
        // write next layer's A in fragment order (fp16)
        constexpr int NKS_OUT = NN / 16;       // 16 / 12
        uint4* Hout = ((MODE == 1) ? g_H1f : g_H2f) + (size_t)tile * NKS_OUT * 256;
        const float* bv = bias + t * NN;
#pragma unroll
        for (int mt = 0; mt < 4; mt++) {
#pragma unroll
            for (int ntp = 0; ntp < NT8 / 2; ntp++) {
                const int nt = 2 * ntp;
                const int c0 = wn * (NN / 4) + nt * 8 + 2 * tig;   // low-half cols
                const int c1 = c0 + 8;                              // high-half cols
                const float bb0 = __ldg(bv + c0), bb1 = __ldg(bv + c0 + 1);
                const float bb2 = __ldg(bv + c1), bb3 = __ldg(bv + c1 + 1);
                uint4 v;
                v.x = pack2(celu_f(acc[mt][nt][0] + bb0),     celu_f(acc[mt][nt][1] + bb1));
                v.y = pack2(celu_f(acc[mt][nt][2] + bb0),     celu_f(acc[mt][nt][3] + bb1));
                v.z = pack2(celu_f(acc[mt][nt + 1][0] + bb2), celu_f(acc[mt][nt + 1][1] + bb3));
                v.w = pack2(celu_f(acc[mt][nt + 1][2] + bb2), celu_f(acc[mt][nt + 1][3] + bb3));
                const int ks = wn * (NT8 / 2) + ntp;
                Hout[(ks * 8 + wm * 4 + mt) * 32 + lane] = v;
            }
        }
    }
}

// ---------------- launch ----------------
#define SM1 (32768 + 2 * H1 * 128)   // 98304
#define SM2 (32768 + 2 * H2 * 128)   // 81920
#define SM3 (32768 + 2 * H3 * 128)   // 73728

extern "C" void kernel_launch(void* const* d_in, const int* in_sizes, int n_in,
                              void* d_out, int out_size) {
    const int*   z     = (const int*)  d_in[0];
    const float* feat  = (const float*)d_in[1];
    const int*   batch = (const int*)  d_in[2];
    const float* W1 = (const float*)d_in[4];
    const float* b1 = (const float*)d_in[5];
    const float* W2 = (const float*)d_in[6];
    const float* b2 = (const float*)d_in[7];
    const float* W3 = (const float*)d_in[8];
    const float* b3 = (const float*)d_in[9];
    const float* W4 = (const float*)d_in[10];
    const float* b4 = (const float*)d_in[11];
    float* out = (float*)d_out;

    cudaFuncSetAttribute(k_gemm<1>, cudaFuncAttributeMaxDynamicSharedMemorySize, SM1);
    cudaFuncSetAttribute(k_gemm<2>, cudaFuncAttributeMaxDynamicSharedMemorySize, SM2);
    cudaFuncSetAttribute(k_gemm<3>, cudaFuncAttributeMaxDynamicSharedMemorySize, SM3);

    const int initN = (out_size > PAD_MAX) ? out_size : PAD_MAX;
    k_init<<<(initN + 255) / 256, 256>>>(z, out, out_size);            // 1
    k_count<<<(N_ATOMS + 255) / 256, 256>>>(z);                        // 2
    k_scan<<<1, 1>>>();                                                // 3
    k_scatter<<<(N_ATOMS + 255) / 256, 256>>>();                       // 4
    dim3 pg((NTILES_MAX * 64 * 8 * 32 + 255) / 256, 2);
    k_prep<<<pg, 256>>>(feat, W1, W2, W3);                             // 5

    dim3 grid(NT_MAX, 5);
    k_gemm<1><<<grid, TPB, SM1>>>(batch, b1, W4, b4, out);             // 6 <- profiled
    k_gemm<2><<<grid, TPB, SM2>>>(batch, b2, W4, b4, out);
    k_gemm<3><<<grid, TPB, SM3>>>(batch, b3, W4, b4, out);
}